// round 13
// baseline (speedup 1.0000x reference)
#include <cuda_runtime.h>
#include <cuda_bf16.h>
#include <math.h>
#include <stdint.h>

#define IN_DIM 256
#define HID    128
#define EPS_C  0.3f
#define MAXN   100000
#define MAXE   1600000

// -------- scratch (static device globals; no allocation) --------
__device__ float  g_h[(size_t)MAXN * HID];
__device__ float  g_pd[MAXN];
__device__ float  g_ps[MAXN];
__device__ float  g_norm[MAXN];
__device__ int    g_deg[MAXN];
__device__ int    g_off[MAXN];
__device__ int    g_cur[MAXN];
__device__ int    g_bsum[512];
__device__ int    g_bscan[512];
__device__ float2 g_csr[MAXE];

// ---------------------------------------------------------------
__global__ void k_zero(int n) {
    int i = blockIdx.x * blockDim.x + threadIdx.x;
    if (i < n) { g_deg[i] = 0; g_cur[i] = 0; }
}

__global__ void k_deg(const int* __restrict__ dst, int E) {
    int i = blockIdx.x * blockDim.x + threadIdx.x;
    if (i < E) atomicAdd(&g_deg[dst[i]], 1);
}

// ---------------------------------------------------------------
__global__ void k_scan1(int n) {
    __shared__ int s[256];
    int t = threadIdx.x, i = blockIdx.x * 256 + t;
    int v = (i < n) ? g_deg[i] : 0;
    s[t] = v; __syncthreads();
#pragma unroll
    for (int o = 1; o < 256; o <<= 1) {
        int x = (t >= o) ? s[t - o] : 0;
        __syncthreads();
        s[t] += x;
        __syncthreads();
    }
    if (i < n) g_off[i] = s[t] - v;
    if (t == 255) g_bsum[blockIdx.x] = s[255];
}
__global__ void k_scan2(int nb) {
    __shared__ int s[512];
    int t = threadIdx.x;
    int v = (t < nb) ? g_bsum[t] : 0;
    s[t] = v; __syncthreads();
#pragma unroll
    for (int o = 1; o < 512; o <<= 1) {
        int x = (t >= o) ? s[t - o] : 0;
        __syncthreads();
        s[t] += x;
        __syncthreads();
    }
    if (t < nb) g_bscan[t] = s[t] - v;
}
__global__ void k_scan3(int n) {
    int i = blockIdx.x * blockDim.x + threadIdx.x;
    if (i < n) {
        g_off[i] += g_bscan[i >> 8];
        float d = (float)g_deg[i];
        if (d < 1.0f) d = 1.0f;
        g_norm[i] = rsqrtf(d);
    }
}

// ---------------------------------------------------------------
// tensor-core GEMM via mma.sync bf16 (3-term compensated), pipelined.
// 512 threads, warp tile 16x64, block tile 128x128, K=256 in 8 chunks of 32.
// A ping-pong (DRAM latency hidden); B single-buffer (L2-resident w1).
// All smem STATIC (48KB exactly) — no dynamic smem, no cudaFuncSetAttribute.
// ---------------------------------------------------------------
#define LDSM_X4(r0, r1, r2, r3, a) \
    asm volatile("ldmatrix.sync.aligned.m8n8.x4.shared.b16 {%0,%1,%2,%3}, [%4];" \
                 : "=r"(r0), "=r"(r1), "=r"(r2), "=r"(r3) : "r"(a))
#define LDSM_X2(r0, r1, a) \
    asm volatile("ldmatrix.sync.aligned.m8n8.x2.shared.b16 {%0,%1}, [%2];" \
                 : "=r"(r0), "=r"(r1) : "r"(a))
#define MMA_BF16(d, a, b) \
    asm volatile("mma.sync.aligned.m16n8k16.row.col.f32.bf16.bf16.f32 " \
                 "{%0,%1,%2,%3}, {%4,%5,%6,%7}, {%8,%9}, {%0,%1,%2,%3};" \
                 : "+f"((d)[0]), "+f"((d)[1]), "+f"((d)[2]), "+f"((d)[3]) \
                 : "r"((a)[0]), "r"((a)[1]), "r"((a)[2]), "r"((a)[3]), \
                   "r"((b)[0]), "r"((b)[1]))

__device__ __forceinline__ uint32_t smem_u32(const void* p) {
    uint32_t a;
    asm("{ .reg .u64 t; cvta.to.shared.u64 t, %1; cvt.u32.u64 %0, t; }"
        : "=r"(a) : "l"(p));
    return a;
}
// byte offset of 16B chunk c (0..3) of row r in a [128 x 64B] tile, XOR-swizzled
__device__ __forceinline__ uint32_t swz(int r, int c) {
    return (uint32_t)((r << 6) + ((c ^ ((r >> 1) & 3)) << 4));
}
__device__ __forceinline__ uint32_t pk(__nv_bfloat16 a, __nv_bfloat16 b) {
    __nv_bfloat162 t; t.x = a; t.y = b;
    return *(uint32_t*)&t;
}
__device__ __forceinline__ void split8(float4 a, float4 b, uint4& hi, uint4& lo) {
    __nv_bfloat16 h0 = __float2bfloat16(a.x), h1 = __float2bfloat16(a.y);
    __nv_bfloat16 h2 = __float2bfloat16(a.z), h3 = __float2bfloat16(a.w);
    __nv_bfloat16 h4 = __float2bfloat16(b.x), h5 = __float2bfloat16(b.y);
    __nv_bfloat16 h6 = __float2bfloat16(b.z), h7 = __float2bfloat16(b.w);
    hi.x = pk(h0, h1); hi.y = pk(h2, h3); hi.z = pk(h4, h5); hi.w = pk(h6, h7);
    lo.x = pk(__float2bfloat16(a.x - __bfloat162float(h0)),
              __float2bfloat16(a.y - __bfloat162float(h1)));
    lo.y = pk(__float2bfloat16(a.z - __bfloat162float(h2)),
              __float2bfloat16(a.w - __bfloat162float(h3)));
    lo.z = pk(__float2bfloat16(b.x - __bfloat162float(h4)),
              __float2bfloat16(b.y - __bfloat162float(h5)));
    lo.w = pk(__float2bfloat16(b.z - __bfloat162float(h6)),
              __float2bfloat16(b.w - __bfloat162float(h7)));
}

struct GemmSmem {
    union {
        struct { uint8_t Ah[2][8192]; uint8_t Al[2][8192]; } a;   // 32 KB
        struct { float spd[128][2]; float sps[128][2]; float sbw[384]; } e;
    } u;
    uint8_t Bh[8192];
    uint8_t Bl[8192];
};   // 49152 bytes total (exactly 48 KB)

__global__ __launch_bounds__(512, 1) void k_gemm_mma(
    const float* __restrict__ x, const float* __restrict__ w1,
    const float* __restrict__ b1, const float* __restrict__ gate_w, int Nn)
{
    __shared__ GemmSmem sm;

    int tid = threadIdx.x, lane = tid & 31, wid = tid >> 5;
    int row0 = blockIdx.x * 128;
    int wm = wid & 7, wn = wid >> 3;
    int m0 = wm * 16, n0 = wn * 64;

    uint32_t bAh = smem_u32(sm.u.a.Ah), bAl = smem_u32(sm.u.a.Al);
    uint32_t bBh = smem_u32(sm.Bh),     bBl = smem_u32(sm.Bl);

    // producer mapping: thread fills a quarter row (8 floats) of x and w tiles
    int pr = tid >> 2, ph = tid & 3;
    const float* xp = x + (size_t)(row0 + pr) * IN_DIM + ph * 8;
    const float* wp = w1 + (size_t)pr * IN_DIM + ph * 8;
    bool xok = (row0 + pr) < Nn;
    uint32_t oS = swz(pr, ph);

    float d[8][4];
#pragma unroll
    for (int i = 0; i < 8; i++)
#pragma unroll
        for (int j = 0; j < 4; j++) d[i][j] = 0.0f;

    int aRow = lane & 15, aCH = lane >> 4;
    int bRow = lane & 7, bCH = (lane >> 3) & 1;

    float4 xv0 = make_float4(0.f, 0.f, 0.f, 0.f), xv1 = xv0, wv0, wv1;

    // prologue: load + convert + store chunk 0 (A -> buf 0, B -> single buf)
    if (xok) { xv0 = *(const float4*)(xp); xv1 = *(const float4*)(xp + 4); }
    wv0 = *(const float4*)(wp);
    wv1 = *(const float4*)(wp + 4);
    {
        uint4 hi, lo;
        split8(xv0, xv1, hi, lo);
        *(uint4*)(sm.u.a.Ah[0] + oS) = hi;  *(uint4*)(sm.u.a.Al[0] + oS) = lo;
        split8(wv0, wv1, hi, lo);
        *(uint4*)(sm.Bh + oS) = hi;  *(uint4*)(sm.Bl + oS) = lo;
    }
    __syncthreads();

    for (int kc = 0; kc < 8; kc++) {
        // prefetch next chunk into registers (LDG overlaps MMA below)
        if (kc < 7) {
            int kb = (kc + 1) * 32;
            xv0 = make_float4(0.f, 0.f, 0.f, 0.f); xv1 = xv0;
            if (xok) { xv0 = *(const float4*)(xp + kb); xv1 = *(const float4*)(xp + kb + 4); }
            wv0 = *(const float4*)(wp + kb);
            wv1 = *(const float4*)(wp + kb + 4);
        }

        // MMA on current A buffer + B buffer
        uint32_t abuf = (uint32_t)(kc & 1) * 8192u;
#pragma unroll
        for (int s = 0; s < 2; s++) {
            int ca = s * 2 + aCH;
            uint32_t oA = swz(m0 + aRow, ca);
            uint32_t ah[4], al[4];
            LDSM_X4(ah[0], ah[1], ah[2], ah[3], bAh + abuf + oA);
            LDSM_X4(al[0], al[1], al[2], al[3], bAl + abuf + oA);
            int cb = s * 2 + bCH;
#pragma unroll
            for (int nt = 0; nt < 8; nt++) {
                uint32_t oB = swz(n0 + nt * 8 + bRow, cb);
                uint32_t bh[2], bl[2];
                LDSM_X2(bh[0], bh[1], bBh + oB);
                LDSM_X2(bl[0], bl[1], bBl + oB);
                MMA_BF16(d[nt], ah, bh);
                MMA_BF16(d[nt], ah, bl);
                MMA_BF16(d[nt], al, bh);
            }
        }
        __syncthreads();   // all warps done reading B (and old A)

        // convert + store next chunk (A -> other buf, B overwrites)
        if (kc < 7) {
            int nb = (kc + 1) & 1;
            uint4 hi, lo;
            split8(xv0, xv1, hi, lo);
            *(uint4*)(sm.u.a.Ah[nb] + oS) = hi;  *(uint4*)(sm.u.a.Al[nb] + oS) = lo;
            split8(wv0, wv1, hi, lo);
            *(uint4*)(sm.Bh + oS) = hi;  *(uint4*)(sm.Bl + oS) = lo;
            __syncthreads();   // stores visible before next MMA
        }
    }
    __syncthreads();   // before epilogue aliases the A buffers

    // ---- epilogue: bias + relu + write h + fused gate params ----
    if (tid < 128) {
        sm.u.e.sbw[tid]       = b1[tid];
        sm.u.e.sbw[128 + tid] = gate_w[tid];
        sm.u.e.sbw[256 + tid] = gate_w[HID + tid];
    }
    __syncthreads();

    int qr = lane >> 2;   // 0..7
    int qc = lane & 3;    // col-pair index
    float ppd0 = 0.f, ppd1 = 0.f, pps0 = 0.f, pps1 = 0.f;
    int r1 = row0 + m0 + qr;     // rows r1 and r1+8
#pragma unroll
    for (int nt = 0; nt < 8; nt++) {
        int c0 = n0 + nt * 8 + qc * 2;
        float bw0 = sm.u.e.sbw[c0], bw1 = sm.u.e.sbw[c0 + 1];
        float wd0 = sm.u.e.sbw[128 + c0], wd1 = sm.u.e.sbw[128 + c0 + 1];
        float ws0 = sm.u.e.sbw[256 + c0], ws1 = sm.u.e.sbw[256 + c0 + 1];
        float* dd = d[nt];
        float h00 = dd[0] + bw0; h00 = h00 > 0.f ? h00 : 0.f;
        float h01 = dd[1] + bw1; h01 = h01 > 0.f ? h01 : 0.f;
        float h10 = dd[2] + bw0; h10 = h10 > 0.f ? h10 : 0.f;
        float h11 = dd[3] + bw1; h11 = h11 > 0.f ? h11 : 0.f;
        if (r1 < Nn)
            *(float2*)(g_h + (size_t)r1 * HID + c0) = make_float2(h00, h01);
        if (r1 + 8 < Nn)
            *(float2*)(g_h + (size_t)(r1 + 8) * HID + c0) = make_float2(h10, h11);
        ppd0 += h00 * wd0 + h01 * wd1;
        ppd1 += h10 * wd0 + h11 * wd1;
        pps0 += h00 * ws0 + h01 * ws1;
        pps1 += h10 * ws0 + h11 * ws1;
    }
#pragma unroll
    for (int m = 1; m < 4; m <<= 1) {
        ppd0 += __shfl_xor_sync(0xffffffffu, ppd0, m);
        ppd1 += __shfl_xor_sync(0xffffffffu, ppd1, m);
        pps0 += __shfl_xor_sync(0xffffffffu, pps0, m);
        pps1 += __shfl_xor_sync(0xffffffffu, pps1, m);
    }
    if (qc == 0) {
        sm.u.e.spd[m0 + qr][wn]     = ppd0;  sm.u.e.sps[m0 + qr][wn]     = pps0;
        sm.u.e.spd[m0 + 8 + qr][wn] = ppd1;  sm.u.e.sps[m0 + 8 + qr][wn] = pps1;
    }
    __syncthreads();
    if (tid < 128) {
        int gr = row0 + tid;
        if (gr < Nn) {
            g_pd[gr] = sm.u.e.spd[tid][0] + sm.u.e.spd[tid][1];
            g_ps[gr] = sm.u.e.sps[tid][0] + sm.u.e.sps[tid][1];
        }
    }
}

// ---------------------------------------------------------------
__global__ void k_fill(const int* __restrict__ ei,
                       const float* __restrict__ gate_b, int E)
{
    int i = blockIdx.x * blockDim.x + threadIdx.x;
    if (i >= E) return;
    int s = ei[i];
    int dn = ei[E + i];
    float g = tanhf(g_pd[dn] + g_ps[s] + gate_b[0]);
    float e = g * g_norm[dn] * g_norm[s];
    int pos = g_off[dn] + atomicAdd(&g_cur[dn], 1);
    g_csr[pos] = make_float2(e, __int_as_float(s));
}

// ---------------------------------------------------------------
__global__ __launch_bounds__(256) void k_agg(float* __restrict__ out, int Nn)
{
    int node = blockIdx.x * 8 + (threadIdx.x >> 5);
    int lane = threadIdx.x & 31;
    if (node >= Nn) return;

    int beg = g_off[node];
    int end = beg + g_deg[node];

    float4 acc0 = make_float4(0.f, 0.f, 0.f, 0.f);
    float4 acc1 = make_float4(0.f, 0.f, 0.f, 0.f);
    float4 acc2 = make_float4(0.f, 0.f, 0.f, 0.f);
    float4 acc3 = make_float4(0.f, 0.f, 0.f, 0.f);

    int t = beg;
    for (; t + 3 < end; t += 4) {
        float2 c0 = g_csr[t];
        float2 c1 = g_csr[t + 1];
        float2 c2 = g_csr[t + 2];
        float2 c3 = g_csr[t + 3];
        float4 h0 = ((const float4*)(g_h + (size_t)__float_as_int(c0.y) * HID))[lane];
        float4 h1 = ((const float4*)(g_h + (size_t)__float_as_int(c1.y) * HID))[lane];
        float4 h2 = ((const float4*)(g_h + (size_t)__float_as_int(c2.y) * HID))[lane];
        float4 h3 = ((const float4*)(g_h + (size_t)__float_as_int(c3.y) * HID))[lane];
        acc0.x += h0.x * c0.x; acc0.y += h0.y * c0.x; acc0.z += h0.z * c0.x; acc0.w += h0.w * c0.x;
        acc1.x += h1.x * c1.x; acc1.y += h1.y * c1.x; acc1.z += h1.z * c1.x; acc1.w += h1.w * c1.x;
        acc2.x += h2.x * c2.x; acc2.y += h2.y * c2.x; acc2.z += h2.z * c2.x; acc2.w += h2.w * c2.x;
        acc3.x += h3.x * c3.x; acc3.y += h3.y * c3.x; acc3.z += h3.z * c3.x; acc3.w += h3.w * c3.x;
    }
    for (; t < end; t++) {
        float2 c0 = g_csr[t];
        float4 h0 = ((const float4*)(g_h + (size_t)__float_as_int(c0.y) * HID))[lane];
        acc0.x += h0.x * c0.x; acc0.y += h0.y * c0.x; acc0.z += h0.z * c0.x; acc0.w += h0.w * c0.x;
    }

    float4 mine = ((const float4*)(g_h + (size_t)node * HID))[lane];
    float4 o;
    o.x = EPS_C * mine.x + ((acc0.x + acc1.x) + (acc2.x + acc3.x));
    o.y = EPS_C * mine.y + ((acc0.y + acc1.y) + (acc2.y + acc3.y));
    o.z = EPS_C * mine.z + ((acc0.z + acc1.z) + (acc2.z + acc3.z));
    o.w = EPS_C * mine.w + ((acc0.w + acc1.w) + (acc2.w + acc3.w));
    ((float4*)(out + (size_t)node * HID))[lane] = o;
}

// ---------------------------------------------------------------
extern "C" void kernel_launch(void* const* d_in, const int* in_sizes, int n_in,
                              void* d_out, int out_size)
{
    const float* x      = (const float*)d_in[0];
    const int*   ei     = (const int*)d_in[1];
    const float* w1     = (const float*)d_in[2];
    const float* b1     = (const float*)d_in[3];
    const float* gate_w = (const float*)d_in[4];
    const float* gate_b = (const float*)d_in[5];
    float* out = (float*)d_out;

    int Nn = in_sizes[0] / IN_DIM;     // 100000
    int E  = in_sizes[1] / 2;          // 1600000
    int nb = (Nn + 255) / 256;         // scan blocks

    // k_gemm_mma kept as launch #4 (ncu -s 5 -c 1 captures launch #4).
    k_zero<<<(Nn + 255) / 256, 256>>>(Nn);                        // 1
    k_deg<<<(E + 255) / 256, 256>>>(ei + E, E);                   // 2
    k_scan1<<<nb, 256>>>(Nn);                                     // 3
    k_gemm_mma<<<(Nn + 127) / 128, 512>>>(x, w1, b1, gate_w, Nn); // 4
    k_scan2<<<1, 512>>>(nb);                                      // 5
    k_scan3<<<(Nn + 255) / 256, 256>>>(Nn);                       // 6
    k_fill<<<(E + 255) / 256, 256>>>(ei, gate_b, E);              // 7
    k_agg<<<(Nn + 7) / 8, 256>>>(out, Nn);                        // 8
}

// round 17
// speedup vs baseline: 1.5142x; 1.5142x over previous
#include <cuda_runtime.h>
#include <cuda_bf16.h>
#include <math.h>
#include <stdint.h>

#define IN_DIM 256
#define HID    128
#define EPS_C  0.3f
#define MAXN   100000
#define MAXE   1600000

// -------- scratch (static device globals; no allocation) --------
__device__ float  g_h[(size_t)MAXN * HID];
__device__ float4 g_p[MAXN];                 // (a_dst, a_src, norm, pad)
__device__ int    g_deg[MAXN];
__device__ int    g_off[MAXN];
__device__ int    g_cur[MAXN];               // seeded with g_off in scan3
__device__ int    g_bsum[512];
__device__ int    g_bscan[512];
__device__ float2 g_csr[MAXE];               // per-edge (e, src_bits) sorted by dst

// ---------------------------------------------------------------
__global__ void k_zero(int n) {
    int i = blockIdx.x * blockDim.x + threadIdx.x;
    if (i < n) g_deg[i] = 0;
}

__global__ void k_deg(const int* __restrict__ dst, int E) {
    int i = blockIdx.x * blockDim.x + threadIdx.x;
    if (i < E) atomicAdd(&g_deg[dst[i]], 1);
}

// ---------------------------------------------------------------
__global__ void k_scan1(int n) {
    __shared__ int s[256];
    int t = threadIdx.x, i = blockIdx.x * 256 + t;
    int v = (i < n) ? g_deg[i] : 0;
    s[t] = v; __syncthreads();
#pragma unroll
    for (int o = 1; o < 256; o <<= 1) {
        int x = (t >= o) ? s[t - o] : 0;
        __syncthreads();
        s[t] += x;
        __syncthreads();
    }
    if (i < n) g_off[i] = s[t] - v;
    if (t == 255) g_bsum[blockIdx.x] = s[255];
}
__global__ void k_scan2(int nb) {
    __shared__ int s[512];
    int t = threadIdx.x;
    int v = (t < nb) ? g_bsum[t] : 0;
    s[t] = v; __syncthreads();
#pragma unroll
    for (int o = 1; o < 512; o <<= 1) {
        int x = (t >= o) ? s[t - o] : 0;
        __syncthreads();
        s[t] += x;
        __syncthreads();
    }
    if (t < nb) g_bscan[t] = s[t] - v;
}
__global__ void k_scan3(int n) {
    int i = blockIdx.x * blockDim.x + threadIdx.x;
    if (i < n) {
        int off = g_off[i] + g_bscan[i >> 8];
        g_off[i] = off;
        g_cur[i] = off;                       // fill cursor = start offset
        float d = (float)g_deg[i];
        if (d < 1.0f) d = 1.0f;
        // .x/.y written by gemm epilogue; write .z (norm) and .w (pad) here
        *(float2*)&g_p[i].z = make_float2(rsqrtf(d), 0.0f);
    }
}

// ---------------------------------------------------------------
// tensor-core GEMM via mma.sync bf16 (3-term compensated).
// 256 threads, warp tile 32x64, block tile 128x128, K=256 in 8 chunks of 32.
// (R8 structure, measured at 96.6us.)
// ---------------------------------------------------------------
#define LDSM_X4(r0, r1, r2, r3, a) \
    asm volatile("ldmatrix.sync.aligned.m8n8.x4.shared.b16 {%0,%1,%2,%3}, [%4];" \
                 : "=r"(r0), "=r"(r1), "=r"(r2), "=r"(r3) : "r"(a))
#define LDSM_X2(r0, r1, a) \
    asm volatile("ldmatrix.sync.aligned.m8n8.x2.shared.b16 {%0,%1}, [%2];" \
                 : "=r"(r0), "=r"(r1) : "r"(a))
#define MMA_BF16(d, a, b) \
    asm volatile("mma.sync.aligned.m16n8k16.row.col.f32.bf16.bf16.f32 " \
                 "{%0,%1,%2,%3}, {%4,%5,%6,%7}, {%8,%9}, {%0,%1,%2,%3};" \
                 : "+f"((d)[0]), "+f"((d)[1]), "+f"((d)[2]), "+f"((d)[3]) \
                 : "r"((a)[0]), "r"((a)[1]), "r"((a)[2]), "r"((a)[3]), \
                   "r"((b)[0]), "r"((b)[1]))

__device__ __forceinline__ uint32_t smem_u32(const void* p) {
    uint32_t a;
    asm("{ .reg .u64 t; cvta.to.shared.u64 t, %1; cvt.u32.u64 %0, t; }"
        : "=r"(a) : "l"(p));
    return a;
}
// byte offset of 16B chunk c (0..3) of row r in a [128 x 64B] tile, XOR-swizzled
__device__ __forceinline__ uint32_t swz(int r, int c) {
    return (uint32_t)((r << 6) + ((c ^ ((r >> 1) & 3)) << 4));
}
__device__ __forceinline__ uint32_t pk(__nv_bfloat16 a, __nv_bfloat16 b) {
    __nv_bfloat162 t; t.x = a; t.y = b;
    return *(uint32_t*)&t;
}
__device__ __forceinline__ void split8(float4 a, float4 b, uint4& hi, uint4& lo) {
    __nv_bfloat16 h0 = __float2bfloat16(a.x), h1 = __float2bfloat16(a.y);
    __nv_bfloat16 h2 = __float2bfloat16(a.z), h3 = __float2bfloat16(a.w);
    __nv_bfloat16 h4 = __float2bfloat16(b.x), h5 = __float2bfloat16(b.y);
    __nv_bfloat16 h6 = __float2bfloat16(b.z), h7 = __float2bfloat16(b.w);
    hi.x = pk(h0, h1); hi.y = pk(h2, h3); hi.z = pk(h4, h5); hi.w = pk(h6, h7);
    lo.x = pk(__float2bfloat16(a.x - __bfloat162float(h0)),
              __float2bfloat16(a.y - __bfloat162float(h1)));
    lo.y = pk(__float2bfloat16(a.z - __bfloat162float(h2)),
              __float2bfloat16(a.w - __bfloat162float(h3)));
    lo.z = pk(__float2bfloat16(b.x - __bfloat162float(h4)),
              __float2bfloat16(b.y - __bfloat162float(h5)));
    lo.w = pk(__float2bfloat16(b.z - __bfloat162float(h6)),
              __float2bfloat16(b.w - __bfloat162float(h7)));
}

__global__ __launch_bounds__(256) void k_gemm_mma(
    const float* __restrict__ x, const float* __restrict__ w1,
    const float* __restrict__ b1, const float* __restrict__ gate_w, int Nn)
{
    __shared__ __align__(16) uint8_t sAh[8192], sAl[8192], sBh[8192], sBl[8192];
    __shared__ float spd[128][2], sps[128][2], sbw[384];

    int tid = threadIdx.x, lane = tid & 31, wid = tid >> 5;
    int row0 = blockIdx.x * 128;
    int wm = wid & 3, wn = wid >> 2;
    int m0 = wm * 32, n0 = wn * 64;

    uint32_t bAh = smem_u32(sAh), bAl = smem_u32(sAl);
    uint32_t bBh = smem_u32(sBh), bBl = smem_u32(sBl);

    // producer mapping: each thread fills half a row per chunk
    int pr = tid >> 1, ph = tid & 1;
    const float* xp = x + (size_t)(row0 + pr) * IN_DIM;
    const float* wp = w1 + (size_t)pr * IN_DIM;
    bool xok = (row0 + pr) < Nn;

    float d[16][4];   // [mt*8+nt][4]
#pragma unroll
    for (int i = 0; i < 16; i++)
#pragma unroll
        for (int j = 0; j < 4; j++) d[i][j] = 0.0f;

    int aRow = lane & 15;          // A: rows m + aRow
    int aCH  = lane >> 4;          // A: chunk high bit
    int bIdx = lane & 15;
    int bRow = bIdx & 7;           // B: rows n + bRow
    int bCH  = bIdx >> 3;          // B: chunk high bit

    for (int kc = 0; kc < 8; kc++) {
        int kb = kc * 32 + ph * 16;
        float4 v0 = make_float4(0.f, 0.f, 0.f, 0.f), v1 = v0, v2, v3;
        if (xok) {
            v0 = *(const float4*)(xp + kb);
            v1 = *(const float4*)(xp + kb + 4);
        }
        v2 = *(const float4*)(wp + kb);
        v3 = *(const float4*)(wp + kb + 4);
        float4 v0b = make_float4(0.f, 0.f, 0.f, 0.f), v1b = v0b, v2b, v3b;
        if (xok) {
            v0b = *(const float4*)(xp + kb + 8);
            v1b = *(const float4*)(xp + kb + 12);
        }
        v2b = *(const float4*)(wp + kb + 8);
        v3b = *(const float4*)(wp + kb + 12);

        uint4 hA0, lA0, hA1, lA1, hB0, lB0, hB1, lB1;
        split8(v0, v1, hA0, lA0);
        split8(v0b, v1b, hA1, lA1);
        split8(v2, v3, hB0, lB0);
        split8(v2b, v3b, hB1, lB1);

        uint32_t o0 = swz(pr, ph * 2), o1 = swz(pr, ph * 2 + 1);
        *(uint4*)(sAh + o0) = hA0;  *(uint4*)(sAh + o1) = hA1;
        *(uint4*)(sAl + o0) = lA0;  *(uint4*)(sAl + o1) = lA1;
        *(uint4*)(sBh + o0) = hB0;  *(uint4*)(sBh + o1) = hB1;
        *(uint4*)(sBl + o0) = lB0;  *(uint4*)(sBl + o1) = lB1;
        __syncthreads();

#pragma unroll
        for (int s = 0; s < 2; s++) {
            int ca = s * 2 + aCH;
            uint32_t oA0 = swz(m0 + aRow, ca);
            uint32_t oA1 = swz(m0 + 16 + aRow, ca);
            uint32_t ah0[4], al0[4], ah1[4], al1[4];
            LDSM_X4(ah0[0], ah0[1], ah0[2], ah0[3], bAh + oA0);
            LDSM_X4(al0[0], al0[1], al0[2], al0[3], bAl + oA0);
            LDSM_X4(ah1[0], ah1[1], ah1[2], ah1[3], bAh + oA1);
            LDSM_X4(al1[0], al1[1], al1[2], al1[3], bAl + oA1);
            int cb = s * 2 + bCH;
#pragma unroll
            for (int nt = 0; nt < 8; nt++) {
                uint32_t oB = swz(n0 + nt * 8 + bRow, cb);
                uint32_t bh[2], bl[2];
                LDSM_X2(bh[0], bh[1], bBh + oB);
                LDSM_X2(bl[0], bl[1], bBl + oB);
                MMA_BF16(d[nt], ah0, bh);
                MMA_BF16(d[nt], ah0, bl);
                MMA_BF16(d[nt], al0, bh);
                MMA_BF16(d[8 + nt], ah1, bh);
                MMA_BF16(d[8 + nt], ah1, bl);
                MMA_BF16(d[8 + nt], al1, bh);
            }
        }
        __syncthreads();
    }

    // ---- epilogue: bias + relu + write h + fused gate params ----
    if (tid < 128) {
        sbw[tid]       = b1[tid];
        sbw[128 + tid] = gate_w[tid];
        sbw[256 + tid] = gate_w[HID + tid];
    }
    __syncthreads();

    int qr = lane >> 2;   // 0..7
    int qc = lane & 3;    // col-pair index
    float ppd[4] = {0.f, 0.f, 0.f, 0.f};
    float pps[4] = {0.f, 0.f, 0.f, 0.f};
#pragma unroll
    for (int mt = 0; mt < 2; mt++) {
        int r1 = row0 + m0 + mt * 16 + qr;   // rows r1 and r1+8
#pragma unroll
        for (int nt = 0; nt < 8; nt++) {
            int c0 = n0 + nt * 8 + qc * 2;
            float bw0 = sbw[c0], bw1 = sbw[c0 + 1];
            float wd0 = sbw[128 + c0], wd1 = sbw[128 + c0 + 1];
            float ws0 = sbw[256 + c0], ws1 = sbw[256 + c0 + 1];
            float* dd = d[mt * 8 + nt];
            float h00 = dd[0] + bw0; h00 = h00 > 0.f ? h00 : 0.f;
            float h01 = dd[1] + bw1; h01 = h01 > 0.f ? h01 : 0.f;
            float h10 = dd[2] + bw0; h10 = h10 > 0.f ? h10 : 0.f;
            float h11 = dd[3] + bw1; h11 = h11 > 0.f ? h11 : 0.f;
            if (r1 < Nn)
                *(float2*)(g_h + (size_t)r1 * HID + c0) = make_float2(h00, h01);
            if (r1 + 8 < Nn)
                *(float2*)(g_h + (size_t)(r1 + 8) * HID + c0) = make_float2(h10, h11);
            ppd[mt * 2 + 0] += h00 * wd0 + h01 * wd1;
            ppd[mt * 2 + 1] += h10 * wd0 + h11 * wd1;
            pps[mt * 2 + 0] += h00 * ws0 + h01 * ws1;
            pps[mt * 2 + 1] += h10 * ws0 + h11 * ws1;
        }
    }
#pragma unroll
    for (int m = 1; m < 4; m <<= 1) {
#pragma unroll
        for (int i = 0; i < 4; i++) {
            ppd[i] += __shfl_xor_sync(0xffffffffu, ppd[i], m);
            pps[i] += __shfl_xor_sync(0xffffffffu, pps[i], m);
        }
    }
    if (qc == 0) {
        spd[m0 + qr][wn]      = ppd[0];  sps[m0 + qr][wn]      = pps[0];
        spd[m0 + 8 + qr][wn]  = ppd[1];  sps[m0 + 8 + qr][wn]  = pps[1];
        spd[m0 + 16 + qr][wn] = ppd[2];  sps[m0 + 16 + qr][wn] = pps[2];
        spd[m0 + 24 + qr][wn] = ppd[3];  sps[m0 + 24 + qr][wn] = pps[3];
    }
    __syncthreads();
    if (tid < 128) {
        int gr = row0 + tid;
        if (gr < Nn) {
            // write (a_dst, a_src) into g_p[gr].xy; .z/.w written by scan3
            *(float2*)&g_p[gr] = make_float2(spd[tid][0] + spd[tid][1],
                                             sps[tid][0] + sps[tid][1]);
        }
    }
}

// ---------------------------------------------------------------
// fill CSR: tanh.approx gate; 2 float4 gathers per edge; cursor atomics.
__global__ void k_fill(const int* __restrict__ ei,
                       const float* __restrict__ gate_b, int E)
{
    int i = blockIdx.x * blockDim.x + threadIdx.x;
    if (i >= E) return;
    int s = ei[i];
    int dn = ei[E + i];
    float4 pd = g_p[dn];
    float4 ps = g_p[s];
    float t = pd.x + ps.y + gate_b[0];
    float g;
    asm("tanh.approx.f32 %0, %1;" : "=f"(g) : "f"(t));
    float e = g * pd.z * ps.z;
    int pos = atomicAdd(&g_cur[dn], 1);
    g_csr[pos] = make_float2(e, __int_as_float(s));
}

// ---------------------------------------------------------------
__global__ __launch_bounds__(256) void k_agg(float* __restrict__ out, int Nn)
{
    int node = blockIdx.x * 8 + (threadIdx.x >> 5);
    int lane = threadIdx.x & 31;
    if (node >= Nn) return;

    int beg = g_off[node];
    int end = beg + g_deg[node];

    float4 acc0 = make_float4(0.f, 0.f, 0.f, 0.f);
    float4 acc1 = make_float4(0.f, 0.f, 0.f, 0.f);
    float4 acc2 = make_float4(0.f, 0.f, 0.f, 0.f);
    float4 acc3 = make_float4(0.f, 0.f, 0.f, 0.f);

    int t = beg;
    for (; t + 3 < end; t += 4) {
        float2 c0 = g_csr[t];
        float2 c1 = g_csr[t + 1];
        float2 c2 = g_csr[t + 2];
        float2 c3 = g_csr[t + 3];
        float4 h0 = ((const float4*)(g_h + (size_t)__float_as_int(c0.y) * HID))[lane];
        float4 h1 = ((const float4*)(g_h + (size_t)__float_as_int(c1.y) * HID))[lane];
        float4 h2 = ((const float4*)(g_h + (size_t)__float_as_int(c2.y) * HID))[lane];
        float4 h3 = ((const float4*)(g_h + (size_t)__float_as_int(c3.y) * HID))[lane];
        acc0.x += h0.x * c0.x; acc0.y += h0.y * c0.x; acc0.z += h0.z * c0.x; acc0.w += h0.w * c0.x;
        acc1.x += h1.x * c1.x; acc1.y += h1.y * c1.x; acc1.z += h1.z * c1.x; acc1.w += h1.w * c1.x;
        acc2.x += h2.x * c2.x; acc2.y += h2.y * c2.x; acc2.z += h2.z * c2.x; acc2.w += h2.w * c2.x;
        acc3.x += h3.x * c3.x; acc3.y += h3.y * c3.x; acc3.z += h3.z * c3.x; acc3.w += h3.w * c3.x;
    }
    for (; t < end; t++) {
        float2 c0 = g_csr[t];
        float4 h0 = ((const float4*)(g_h + (size_t)__float_as_int(c0.y) * HID))[lane];
        acc0.x += h0.x * c0.x; acc0.y += h0.y * c0.x; acc0.z += h0.z * c0.x; acc0.w += h0.w * c0.x;
    }

    float4 mine = ((const float4*)(g_h + (size_t)node * HID))[lane];
    float4 o;
    o.x = EPS_C * mine.x + ((acc0.x + acc1.x) + (acc2.x + acc3.x));
    o.y = EPS_C * mine.y + ((acc0.y + acc1.y) + (acc2.y + acc3.y));
    o.z = EPS_C * mine.z + ((acc0.z + acc1.z) + (acc2.z + acc3.z));
    o.w = EPS_C * mine.w + ((acc0.w + acc1.w) + (acc2.w + acc3.w));
    ((float4*)(out + (size_t)node * HID))[lane] = o;
}

// ---------------------------------------------------------------
extern "C" void kernel_launch(void* const* d_in, const int* in_sizes, int n_in,
                              void* d_out, int out_size)
{
    const float* x      = (const float*)d_in[0];
    const int*   ei     = (const int*)d_in[1];
    const float* w1     = (const float*)d_in[2];
    const float* b1     = (const float*)d_in[3];
    const float* gate_w = (const float*)d_in[4];
    const float* gate_b = (const float*)d_in[5];
    float* out = (float*)d_out;

    int Nn = in_sizes[0] / IN_DIM;     // 100000
    int E  = in_sizes[1] / 2;          // 1600000
    int nb = (Nn + 255) / 256;         // scan blocks

    // k_gemm_mma kept as launch #4 (ncu -s 5 -c 1 captures launch #4).
    k_zero<<<(Nn + 255) / 256, 256>>>(Nn);                        // 1
    k_deg<<<(E + 255) / 256, 256>>>(ei + E, E);                   // 2
    k_scan1<<<nb, 256>>>(Nn);                                     // 3
    k_gemm_mma<<<(Nn + 127) / 128, 256>>>(x, w1, b1, gate_w, Nn); // 4 <- profiled
    k_scan2<<<1, 512>>>(nb);                                      // 5
    k_scan3<<<(Nn + 255) / 256, 256>>>(Nn);                       // 6
    k_fill<<<(E + 255) / 256, 256>>>(ei, gate_b, E);              // 7
    k_agg<<<(Nn + 7) / 8, 256>>>(out, Nn);                        // 8
}